// round 10
// baseline (speedup 1.0000x reference)
#include <cuda_runtime.h>
#include <cuda_bf16.h>
#include <cstdint>
#include <math.h>

// Problem constants
#define NB     4
#define SQ     2048
#define DIMM   1024
#define INNERD 1024
#define MTOK   (NB * SQ)          // 8192

// Scratch (allocation-free rule: __device__ globals).
__device__ __align__(256) float g_qkv[(size_t)MTOK * 3 * INNERD];   // 96 MB
__device__ __align__(256) float g_att[(size_t)NB * SQ * SQ];        // 64 MB
__device__ __align__(256) float g_ao [(size_t)MTOK * INNERD];       // 32 MB

// ---------------- helpers ----------------
__device__ __forceinline__ uint32_t smem_u32(const void* p) {
    uint32_t a;
    asm("{ .reg .u64 t; cvta.to.shared.u64 t, %1; cvt.u32.u64 %0, t; }" : "=r"(a) : "l"(p));
    return a;
}

// Split 2 fp32 -> packed bf16 hi + bf16 lo (residual). Low 16 bits = first elem.
__device__ __forceinline__ void split2(float x0, float x1, unsigned& h, unsigned& l) {
    __nv_bfloat162 hh = __floats2bfloat162_rn(x0, x1);
    float r0 = x0 - __low2float(hh);
    float r1 = x1 - __high2float(hh);
    __nv_bfloat162 ll = __floats2bfloat162_rn(r0, r1);
    h = *reinterpret_cast<unsigned*>(&hh);
    l = *reinterpret_cast<unsigned*>(&ll);
}
// 8 consecutive fp32 (4 float2) -> uint4 hi + uint4 lo
__device__ __forceinline__ void split8(const float2* s, uint4& h, uint4& l) {
    split2(s[0].x, s[0].y, h.x, l.x);
    split2(s[1].x, s[1].y, h.y, l.y);
    split2(s[2].x, s[2].y, h.z, l.z);
    split2(s[3].x, s[3].y, h.w, l.w);
}

__device__ __forceinline__ void mma16(float* c, const unsigned* a, unsigned b0, unsigned b1) {
    asm volatile(
        "mma.sync.aligned.m16n8k16.row.col.f32.bf16.bf16.f32 "
        "{%0,%1,%2,%3}, {%4,%5,%6,%7}, {%8,%9}, {%0,%1,%2,%3};\n"
        : "+f"(c[0]), "+f"(c[1]), "+f"(c[2]), "+f"(c[3])
        : "r"(a[0]), "r"(a[1]), "r"(a[2]), "r"(a[3]), "r"(b0), "r"(b1));
}

__device__ __forceinline__ void ldsm4(uint32_t addr, unsigned* r) {
    asm volatile("ldmatrix.sync.aligned.m8n8.x4.shared.b16 {%0,%1,%2,%3}, [%4];"
        : "=r"(r[0]), "=r"(r[1]), "=r"(r[2]), "=r"(r[3]) : "r"(addr));
}

// Swizzled byte offset in a [rows][128 bytes] tile, 16B-group q in 0..7.
// Groups 0-3 = bf16 HI (k 0..31), groups 4-7 = bf16 LO (k 0..31).
__device__ __forceinline__ int swoff(int row, int q) {
    return row * 128 + (((unsigned)(q << 4)) ^ (((unsigned)row & 7) << 4));
}

// ---------------- 3xBF16 GEMM ----------------
// C = alpha * (A @ opB) (+ bias).
//   BT=true : B stored [N,K] row-major -> C = A @ B^T
//   BT=false: B stored [K,N] row-major -> C = A @ B
// CTA tile 128(M) x 256(N), K-chunk 32. 256 threads = 8 warps, 2(m) x 4(n),
// warp tile 64x64. Static SMEM: A 16KB + B 32KB = 48KB (hi|lo packed rows).
// Global accesses <=8B only (proven safe on harness pointers).
template <bool BT>
__global__ __launch_bounds__(256, 1)
void gemm_bf3(const float* __restrict__ A, const float* __restrict__ B,
              float* __restrict__ C, const float* __restrict__ bias,
              int K, int lda, int ldb, int ldc,
              long long sA, long long sB, long long sC, float alpha)
{
    __shared__ __align__(128) char tA[16384];   // 128 rows x 128B
    __shared__ __align__(128) char tB[32768];   // 256 rows x 128B
    const uint32_t sbA = smem_u32(tA);
    const uint32_t sbB = smem_u32(tB);

    const int tid = threadIdx.x;
    const int m0 = blockIdx.y * 128;
    const int n0 = blockIdx.x * 256;
    A += (long long)blockIdx.z * sA;
    B += (long long)blockIdx.z * sB;
    C += (long long)blockIdx.z * sC;

    const int warp = tid >> 5, lane = tid & 31;
    const int wm = warp >> 2;          // 0..1
    const int wn = warp & 3;           // 0..3

    // ---- fill mappings (phase-conflict-free: 8 threads/phase -> 8 rows) ----
    const int arow = tid & 127;        // A row
    const int akh  = tid >> 7;         // A k16-half (0: k0-15, 1: k16-31)
    const int brow = tid;              // B(NT) row / B(NN) n-col

    float2 stA[8];                     // 16 floats (A half-row)
    float2 stB[16];                    // 32 floats (B NT full row)
    float  stBn[32];                   // 32 floats (B NN column)

    auto load_chunk = [&](int k0) {
        {
            const float* p = A + (long long)(m0 + arow) * lda + k0 + 16 * akh;
            #pragma unroll
            for (int j = 0; j < 8; j++) stA[j] = *(const float2*)(p + 2 * j);
        }
        if (BT) {
            const float* p = B + (long long)(n0 + brow) * ldb + k0;
            #pragma unroll
            for (int j = 0; j < 16; j++) stB[j] = *(const float2*)(p + 2 * j);
        } else {
            const float* p = B + (long long)k0 * ldb + n0 + brow;
            #pragma unroll
            for (int j = 0; j < 32; j++) stBn[j] = p[(long long)j * ldb];
        }
    };

    auto sts_chunk = [&]() {
        {
            uint4 h, l;
            int q = 2 * akh;
            split8(stA,     h, l);
            *(uint4*)(tA + swoff(arow, q))         = h;
            *(uint4*)(tA + swoff(arow, q + 4))     = l;
            split8(stA + 4, h, l);
            *(uint4*)(tA + swoff(arow, q + 1))     = h;
            *(uint4*)(tA + swoff(arow, q + 5))     = l;
        }
        if (BT) {
            #pragma unroll
            for (int q = 0; q < 4; q++) {
                uint4 h, l;
                split8(stB + 4 * q, h, l);
                *(uint4*)(tB + swoff(brow, q))     = h;
                *(uint4*)(tB + swoff(brow, q + 4)) = l;
            }
        } else {
            #pragma unroll
            for (int q = 0; q < 4; q++) {
                uint4 h, l;
                split2(stBn[8*q+0], stBn[8*q+1], h.x, l.x);
                split2(stBn[8*q+2], stBn[8*q+3], h.y, l.y);
                split2(stBn[8*q+4], stBn[8*q+5], h.z, l.z);
                split2(stBn[8*q+6], stBn[8*q+7], h.w, l.w);
                *(uint4*)(tB + swoff(brow, q))     = h;
                *(uint4*)(tB + swoff(brow, q + 4)) = l;
            }
        }
    };

    // ---- ldmatrix address components ----
    const int l15 = lane & 15;
    const int lh  = (lane >> 4) << 4;          // 0 or 16 bytes (k-half of k16)
    const int s   = (l15 & 7) << 4;            // swizzle XOR
    const int rA0 = (wm * 64 + l15) * 128;     // A rows; + mi*16*128
    const int rB0 = (wn * 64 + l15) * 128;     // B rows; + p*16*128

    float acc[4][8][4] = {};

    const int nchunks = K >> 5;
    load_chunk(0);

    for (int c = 0; c < nchunks; c++) {
        __syncthreads();               // previous chunk fully consumed
        sts_chunk();
        __syncthreads();
        if (c + 1 < nchunks) load_chunk((c + 1) << 5);   // LDGs overlap compute

        #pragma unroll
        for (int ks = 0; ks < 2; ks++) {
            const int xh = ((ks << 5) + lh) ^ s;         // hi region bytes 0-63
            const int xl = (64 + (ks << 5) + lh) ^ s;    // lo region bytes 64-127
            // B fragments for full n64 (held across mi)
            unsigned bh[4][4], bl[4][4];
            #pragma unroll
            for (int p = 0; p < 4; p++) {
                ldsm4(sbB + rB0 + p * 2048 + xh, bh[p]);
                ldsm4(sbB + rB0 + p * 2048 + xl, bl[p]);
            }
            // Stream A fragments per m16
            #pragma unroll
            for (int mi = 0; mi < 4; mi++) {
                unsigned ah[4], al[4];
                ldsm4(sbA + rA0 + mi * 2048 + xh, ah);
                ldsm4(sbA + rA0 + mi * 2048 + xl, al);
                #pragma unroll
                for (int p = 0; p < 4; p++) {
                    mma16(acc[mi][2*p  ], ah, bh[p][0], bh[p][2]);
                    mma16(acc[mi][2*p+1], ah, bh[p][1], bh[p][3]);
                    mma16(acc[mi][2*p  ], ah, bl[p][0], bl[p][2]);
                    mma16(acc[mi][2*p+1], ah, bl[p][1], bl[p][3]);
                    mma16(acc[mi][2*p  ], al, bh[p][0], bh[p][2]);
                    mma16(acc[mi][2*p+1], al, bh[p][1], bh[p][3]);
                }
            }
        }
    }

    // ---- epilogue: direct fragment stores (float2 = 8B, proven safe) ----
    const int gid = lane >> 2, tig = lane & 3;
    #pragma unroll
    for (int mi = 0; mi < 4; mi++) {
        #pragma unroll
        for (int ni = 0; ni < 8; ni++) {
            const int col  = n0 + wn * 64 + ni * 8 + 2 * tig;
            const int row0 = m0 + wm * 64 + mi * 16 + gid;
            float b0v = bias ? bias[col]     : 0.f;
            float b1v = bias ? bias[col + 1] : 0.f;
            float2 v0 = make_float2(acc[mi][ni][0] * alpha + b0v,
                                    acc[mi][ni][1] * alpha + b1v);
            float2 v1 = make_float2(acc[mi][ni][2] * alpha + b0v,
                                    acc[mi][ni][3] * alpha + b1v);
            *(float2*)(C + (long long)row0 * ldc + col)       = v0;
            *(float2*)(C + (long long)(row0 + 8) * ldc + col) = v1;
        }
    }
}

// ---------------- softmax (float2 I/O) ----------------
__global__ __launch_bounds__(256)
void softmax_rows(float* __restrict__ P)
{
    float* row = P + (long long)blockIdx.x * 2048;
    const int t = threadIdx.x;
    float2 v[4];
    float mx = -1e30f;
    #pragma unroll
    for (int j = 0; j < 4; j++) {
        v[j] = *(float2*)(row + 2 * (t + j * 256));
        mx = fmaxf(mx, fmaxf(v[j].x, v[j].y));
    }

    __shared__ float red[256];
    red[t] = mx; __syncthreads();
    for (int s = 128; s > 0; s >>= 1) {
        if (t < s) red[t] = fmaxf(red[t], red[t + s]);
        __syncthreads();
    }
    mx = red[0]; __syncthreads();

    float sum = 0.f;
    #pragma unroll
    for (int j = 0; j < 4; j++) {
        v[j].x = __expf(v[j].x - mx);
        v[j].y = __expf(v[j].y - mx);
        sum += v[j].x + v[j].y;
    }
    red[t] = sum; __syncthreads();
    for (int s = 128; s > 0; s >>= 1) {
        if (t < s) red[t] += red[t + s];
        __syncthreads();
    }
    const float inv = 1.f / red[0];
    #pragma unroll
    for (int j = 0; j < 4; j++) {
        v[j].x *= inv; v[j].y *= inv;
        *(float2*)(row + 2 * (t + j * 256)) = v[j];
    }
}

// ---------------- launch ----------------
extern "C" void kernel_launch(void* const* d_in, const int* in_sizes, int n_in,
                              void* d_out, int out_size)
{
    const float* x    = (const float*)d_in[0];   // [4, 2048, 1024]
    const float* Wqkv = (const float*)d_in[1];   // [1024, 3072]
    const float* Wout = (const float*)d_in[2];   // [1024, 1024]
    const float* bout = (const float*)d_in[3];   // [1024]
    float* out = (float*)d_out;                  // [4, 2048, 1024]

    float *qkv, *att, *ao;
    cudaGetSymbolAddress((void**)&qkv, g_qkv);
    cudaGetSymbolAddress((void**)&att, g_att);
    cudaGetSymbolAddress((void**)&ao,  g_ao);

    const dim3 blk(256);
    const long long sQK = (long long)SQ * 3 * INNERD;
    const long long sAT = (long long)SQ * SQ;
    const long long sAO = (long long)SQ * INNERD;

    // 1) qkv = x @ W_qkv            [8192,1024]x[1024,3072] (NN)
    gemm_bf3<false><<<dim3(3 * INNERD / 256, MTOK / 128, 1), blk>>>(
        x, Wqkv, qkv, nullptr,
        DIMM, DIMM, 3 * INNERD, 3 * INNERD, 0, 0, 0, 1.f);

    // 2) logits = (Q @ K^T) * scale, per batch (NT)
    gemm_bf3<true><<<dim3(SQ / 256, SQ / 128, NB), blk>>>(
        qkv, qkv + INNERD, att, nullptr,
        INNERD, 3 * INNERD, 3 * INNERD, SQ, sQK, sQK, sAT, 0.125f);

    // 3) softmax rows
    softmax_rows<<<NB * SQ, blk>>>(att);

    // 4) ao = attn @ V, per batch (NN, V ld 3072)
    gemm_bf3<false><<<dim3(INNERD / 256, SQ / 128, NB), blk>>>(
        att, qkv + 2 * INNERD, ao, nullptr,
        SQ, SQ, 3 * INNERD, INNERD, sAT, sQK, sAO, 1.f);

    // 5) out = ao @ W_out + b_out (NN)
    gemm_bf3<false><<<dim3(DIMM / 256, MTOK / 128, 1), blk>>>(
        ao, Wout, out, bout,
        INNERD, INNERD, DIMM, DIMM, 0, 0, 0, 1.f);
}

// round 12
// speedup vs baseline: 1.7584x; 1.7584x over previous
#include <cuda_runtime.h>
#include <cuda_bf16.h>
#include <cstdint>
#include <math.h>

// Problem constants
#define NB     4
#define SQ     2048
#define DIMM   1024
#define INNERD 1024
#define MTOK   (NB * SQ)          // 8192

typedef __nv_bfloat16  bf16;
typedef __nv_bfloat162 bf162;

// ---------------- scratch (allocation-free rule: __device__ globals) ----------------
__device__ __align__(256) float g_qkv [(size_t)MTOK * 3 * INNERD];   // 96 MB fp32
__device__ __align__(256) float g_att [(size_t)MTOK * SQ];           // 64 MB fp32
__device__ __align__(256) bf16  g_x2  [(size_t)MTOK * 3 * DIMM];     // A-style split of x
__device__ __align__(256) bf16  g_q2  [(size_t)MTOK * 3 * INNERD];   // A-style split of Q
__device__ __align__(256) bf16  g_k2  [(size_t)MTOK * 3 * INNERD];   // B-style split of K
__device__ __align__(256) bf16  g_v2  [(size_t)NB * INNERD * 3 * SQ];// B-style transposed V
__device__ __align__(256) bf16  g_at2 [(size_t)MTOK * 3 * SQ];       // A-style split of attn
__device__ __align__(256) bf16  g_ao2 [(size_t)MTOK * 3 * INNERD];   // A-style split of attn@V
__device__ __align__(256) bf16  g_wq2 [(size_t)(3 * INNERD) * (3 * DIMM)]; // [3072, 3072]  (round-10 bug: was /3)
__device__ __align__(256) bf16  g_wo2 [(size_t)DIMM * 3 * INNERD];   // [1024, 3072]

// ---------------- helpers ----------------
__device__ __forceinline__ uint32_t smem_u32(const void* p) {
    uint32_t a;
    asm("{ .reg .u64 t; cvta.to.shared.u64 t, %1; cvt.u32.u64 %0, t; }" : "=r"(a) : "l"(p));
    return a;
}
__device__ __forceinline__ void cpa16(uint32_t dst, const void* src) {
    asm volatile("cp.async.cg.shared.global [%0], [%1], 16;" :: "r"(dst), "l"(src));
}
__device__ __forceinline__ void cpa_commit() { asm volatile("cp.async.commit_group;"); }
__device__ __forceinline__ void cpa_wait1()  { asm volatile("cp.async.wait_group 1;" ::: "memory"); }

__device__ __forceinline__ void mma16(float* c, const unsigned* a, unsigned b0, unsigned b1) {
    asm volatile(
        "mma.sync.aligned.m16n8k16.row.col.f32.bf16.bf16.f32 "
        "{%0,%1,%2,%3}, {%4,%5,%6,%7}, {%8,%9}, {%0,%1,%2,%3};\n"
        : "+f"(c[0]), "+f"(c[1]), "+f"(c[2]), "+f"(c[3])
        : "r"(a[0]), "r"(a[1]), "r"(a[2]), "r"(a[3]), "r"(b0), "r"(b1));
}
__device__ __forceinline__ void ldsm4(uint32_t addr, unsigned* r) {
    asm volatile("ldmatrix.sync.aligned.m8n8.x4.shared.b16 {%0,%1,%2,%3}, [%4];"
        : "=r"(r[0]), "=r"(r[1]), "=r"(r[2]), "=r"(r[3]) : "r"(addr));
}
// swizzled byte offset in a [rows][64 bytes] tile, 16B-group q in 0..3
__device__ __forceinline__ int sw64(int row, int q) {
    return row * 64 + ((((unsigned)q) ^ (((unsigned)row >> 1) & 3)) << 4);
}
__device__ __forceinline__ void splitf2(float x, float y, bf162& h, bf162& l) {
    h = __floats2bfloat162_rn(x, y);
    l = __floats2bfloat162_rn(x - __low2float(h), y - __high2float(h));
}

// ---------------- plain bf16 NT GEMM, cp.async 3-stage pipeline ----------------
// C = alpha * A @ B^T (+bias)   A [M,Kp] bf16 ld lda, B [N,Kp] bf16 ld ldb.
// EPI 0: fp32 C.  EPI 1: bf16 split A-style output [h | l | h] with segment segN.
// CTA 128x128, KC=32, 128 threads = 4 warps (2m x 2n), warp tile 64x64.
template <int EPI>
__global__ __launch_bounds__(128)
void gemm_nt(const bf16* __restrict__ A, const bf16* __restrict__ B,
             float* __restrict__ C, bf16* __restrict__ C2,
             const float* __restrict__ bias,
             int Kp, int lda, int ldb, int ldc, int segN,
             long long bA, long long bB, long long bC, float alpha)
{
    __shared__ __align__(128) char sA[3 * 8192];
    __shared__ __align__(128) char sB[3 * 8192];
    const uint32_t uA = smem_u32(sA), uB = smem_u32(sB);

    const int tid = threadIdx.x;
    const int m0 = blockIdx.y * 128, n0 = blockIdx.x * 128;
    A += (long long)blockIdx.z * bA;
    B += (long long)blockIdx.z * bB;

    const int warp = tid >> 5, lane = tid & 31;
    const int wm = warp >> 1, wn = warp & 1;

    // fill mapping: idx = tid + 128*i, row = idx>>2, q = idx&3  (conflict-free)
    const int frow = tid >> 2;
    const int fq   = tid & 3;

    auto fill = [&](int st, int k0) {
        const uint32_t da = uA + st * 8192, db = uB + st * 8192;
        #pragma unroll
        for (int i = 0; i < 4; i++) {
            int r = frow + i * 32;
            cpa16(da + sw64(r, fq), A + (long long)(m0 + r) * lda + k0 + 8 * fq);
            cpa16(db + sw64(r, fq), B + (long long)(n0 + r) * ldb + k0 + 8 * fq);
        }
        cpa_commit();
    };

    // ldmatrix components
    const int l15 = lane & 15;
    const int klh = lane >> 4;                    // k-half of k16 (0/1)
    const int sx  = ((l15 >> 1) & 3) << 4;        // swizzle XOR
    const int rA  = (wm * 64 + l15) * 64;
    const int rB  = (wn * 64 + l15) * 64;

    float acc[4][8][4] = {};

    const int nch = Kp >> 5;
    fill(0, 0);
    fill(1, 32);

    for (int c = 0; c < nch; c++) {
        const int st = c % 3;
        cpa_wait1();                 // stage c data arrived
        __syncthreads();             // all warps done with stage (c+2)%3 from iter c-1
        if (c + 2 < nch) fill((c + 2) % 3, (c + 2) << 5);
        else             cpa_commit();       // keep group accounting aligned

        const uint32_t a0 = uA + st * 8192, b0 = uB + st * 8192;
        #pragma unroll
        for (int ks = 0; ks < 2; ks++) {
            const int xo = ((((ks << 1) + klh)) << 4) ^ sx;
            unsigned bh[4][4];
            #pragma unroll
            for (int p = 0; p < 4; p++) ldsm4(b0 + rB + p * 1024 + xo, bh[p]);
            #pragma unroll
            for (int mi = 0; mi < 4; mi++) {
                unsigned a[4];
                ldsm4(a0 + rA + mi * 1024 + xo, a);
                #pragma unroll
                for (int p = 0; p < 4; p++) {
                    mma16(acc[mi][2 * p    ], a, bh[p][0], bh[p][2]);
                    mma16(acc[mi][2 * p + 1], a, bh[p][1], bh[p][3]);
                }
            }
        }
    }

    // ---- epilogue ----
    const int gid = lane >> 2, tig = lane & 3;
    if (EPI == 0) {
        C += (long long)blockIdx.z * bC;
        #pragma unroll
        for (int mi = 0; mi < 4; mi++) {
            #pragma unroll
            for (int ni = 0; ni < 8; ni++) {
                const int col  = n0 + wn * 64 + ni * 8 + 2 * tig;
                const int row0 = m0 + wm * 64 + mi * 16 + gid;
                float b0v = bias ? bias[col]     : 0.f;
                float b1v = bias ? bias[col + 1] : 0.f;
                float2 v0 = make_float2(acc[mi][ni][0] * alpha + b0v,
                                        acc[mi][ni][1] * alpha + b1v);
                float2 v1 = make_float2(acc[mi][ni][2] * alpha + b0v,
                                        acc[mi][ni][3] * alpha + b1v);
                *(float2*)(C + (long long)row0 * ldc + col)       = v0;
                *(float2*)(C + (long long)(row0 + 8) * ldc + col) = v1;
            }
        }
    } else {
        C2 += (long long)blockIdx.z * bC;
        #pragma unroll
        for (int mi = 0; mi < 4; mi++) {
            #pragma unroll
            for (int ni = 0; ni < 8; ni++) {
                const int col  = n0 + wn * 64 + ni * 8 + 2 * tig;
                const int row0 = m0 + wm * 64 + mi * 16 + gid;
                bf162 h2, l2;
                splitf2(acc[mi][ni][0], acc[mi][ni][1], h2, l2);
                bf16* p0 = C2 + (long long)row0 * ldc + col;
                *(bf162*)p0            = h2;
                *(bf162*)(p0 + segN)   = l2;
                *(bf162*)(p0 + 2*segN) = h2;
                splitf2(acc[mi][ni][2], acc[mi][ni][3], h2, l2);
                bf16* p1 = C2 + (long long)(row0 + 8) * ldc + col;
                *(bf162*)p1            = h2;
                *(bf162*)(p1 + segN)   = l2;
                *(bf162*)(p1 + 2*segN) = h2;
            }
        }
    }
}

// ---------------- split kernels ----------------
// Row-major split: in fp32 [R,C] (ld ldin) -> out bf16 [R,3C].
// STYLE 0 (A-side): [h | l | h]   STYLE 1 (B-side): [h | h | l]
template <int STYLE>
__global__ __launch_bounds__(256)
void split_rm(const float* __restrict__ in, bf16* __restrict__ out, int C, int ldin)
{
    const int r = blockIdx.y;
    const int j = (blockIdx.x * 256 + threadIdx.x) * 2;
    float2 v = *(const float2*)(in + (long long)r * ldin + j);
    bf162 h2, l2;
    splitf2(v.x, v.y, h2, l2);
    bf16* o = out + (long long)r * 3 * C + j;
    *(bf162*)o = h2;
    if (STYLE == 0) { *(bf162*)(o + C) = l2; *(bf162*)(o + 2 * C) = h2; }
    else            { *(bf162*)(o + C) = h2; *(bf162*)(o + 2 * C) = l2; }
}

// Transpose split (B-style): in fp32 [Krows, N] (ld ldin) -> out bf16 [N, 3*Kd].
__global__ __launch_bounds__(256)
void split_tr(const float* __restrict__ in, bf16* __restrict__ out,
              int ldin, int Kd, long long bIn, long long bOut)
{
    __shared__ float t[32][33];
    in  += (long long)blockIdx.z * bIn;
    out += (long long)blockIdx.z * bOut;
    const int k0 = blockIdx.y * 32, nn0 = blockIdx.x * 32;
    const int tx = threadIdx.x & 31, ty = threadIdx.x >> 5;
    #pragma unroll
    for (int i = 0; i < 4; i++)
        t[ty + 8 * i][tx] = in[(long long)(k0 + ty + 8 * i) * ldin + nn0 + tx];
    __syncthreads();
    #pragma unroll
    for (int i = 0; i < 4; i++) {
        float v = t[tx][ty + 8 * i];
        bf16 h = __float2bfloat16(v);
        bf16 l = __float2bfloat16(v - __bfloat162float(h));
        bf16* o = out + (long long)(nn0 + ty + 8 * i) * (3 * Kd) + k0 + tx;
        o[0] = h; o[Kd] = h; o[2 * Kd] = l;
    }
}

// ---------------- softmax + A-style split (fp32 [8192,2048] -> bf16 [8192,6144]) ----------------
__global__ __launch_bounds__(256)
void softmax_split(const float* __restrict__ att, bf16* __restrict__ out)
{
    const long long r = blockIdx.x;
    const float* row = att + r * 2048;
    bf16* orow = out + r * 6144;
    const int t = threadIdx.x;
    float2 v[4];
    float mx = -1e30f;
    #pragma unroll
    for (int j = 0; j < 4; j++) {
        v[j] = *(const float2*)(row + 2 * (t + j * 256));
        mx = fmaxf(mx, fmaxf(v[j].x, v[j].y));
    }
    __shared__ float red[256];
    red[t] = mx; __syncthreads();
    for (int s = 128; s > 0; s >>= 1) {
        if (t < s) red[t] = fmaxf(red[t], red[t + s]);
        __syncthreads();
    }
    mx = red[0]; __syncthreads();
    float sum = 0.f;
    #pragma unroll
    for (int j = 0; j < 4; j++) {
        v[j].x = __expf(v[j].x - mx);
        v[j].y = __expf(v[j].y - mx);
        sum += v[j].x + v[j].y;
    }
    red[t] = sum; __syncthreads();
    for (int s = 128; s > 0; s >>= 1) {
        if (t < s) red[t] += red[t + s];
        __syncthreads();
    }
    const float inv = 1.f / red[0];
    #pragma unroll
    for (int j = 0; j < 4; j++) {
        const int idx = 2 * (t + j * 256);
        bf162 h2, l2;
        splitf2(v[j].x * inv, v[j].y * inv, h2, l2);
        *(bf162*)(orow + idx)        = h2;
        *(bf162*)(orow + 2048 + idx) = l2;
        *(bf162*)(orow + 4096 + idx) = h2;
    }
}

// ---------------- launch ----------------
extern "C" void kernel_launch(void* const* d_in, const int* in_sizes, int n_in,
                              void* d_out, int out_size)
{
    const float* x    = (const float*)d_in[0];   // [4, 2048, 1024]
    const float* Wqkv = (const float*)d_in[1];   // [1024, 3072]
    const float* Wout = (const float*)d_in[2];   // [1024, 1024]
    const float* bout = (const float*)d_in[3];   // [1024]
    float* out = (float*)d_out;                  // [4, 2048, 1024]

    float *qkv, *att;
    bf16 *x2, *q2, *k2, *v2, *at2, *ao2, *wq2, *wo2;
    cudaGetSymbolAddress((void**)&qkv, g_qkv);
    cudaGetSymbolAddress((void**)&att, g_att);
    cudaGetSymbolAddress((void**)&x2,  g_x2);
    cudaGetSymbolAddress((void**)&q2,  g_q2);
    cudaGetSymbolAddress((void**)&k2,  g_k2);
    cudaGetSymbolAddress((void**)&v2,  g_v2);
    cudaGetSymbolAddress((void**)&at2, g_at2);
    cudaGetSymbolAddress((void**)&ao2, g_ao2);
    cudaGetSymbolAddress((void**)&wq2, g_wq2);
    cudaGetSymbolAddress((void**)&wo2, g_wo2);

    // 0) operand splits of the inputs
    split_rm<0><<<dim3(DIMM / 512, MTOK), 256>>>(x, x2, DIMM, DIMM);
    split_tr<<<dim3(3 * INNERD / 32, DIMM / 32, 1), 256>>>(Wqkv, wq2, 3 * INNERD, DIMM, 0, 0);
    split_tr<<<dim3(DIMM / 32, INNERD / 32, 1), 256>>>(Wout, wo2, DIMM, INNERD, 0, 0);

    // 1) qkv = x @ Wqkv          (M=8192, N=3072, K'=3072)
    gemm_nt<0><<<dim3(3 * INNERD / 128, MTOK / 128, 1), 128>>>(
        x2, wq2, qkv, nullptr, nullptr,
        3 * DIMM, 3 * DIMM, 3 * DIMM, 3 * INNERD, 0, 0, 0, 0, 1.f);

    // 2) splits of Q, K, V from qkv
    split_rm<0><<<dim3(2, MTOK), 256>>>(qkv,        q2, INNERD, 3 * INNERD);
    split_rm<1><<<dim3(2, MTOK), 256>>>(qkv + 1024, k2, INNERD, 3 * INNERD);
    split_tr<<<dim3(INNERD / 32, SQ / 32, NB), 256>>>(
        qkv + 2048, v2, 3 * INNERD, SQ,
        (long long)SQ * 3 * INNERD, (long long)INNERD * 3 * SQ);

    // 3) att = 0.125 * Q @ K^T   (per batch, M=N=2048, K'=3072)
    gemm_nt<0><<<dim3(SQ / 128, SQ / 128, NB), 128>>>(
        q2, k2, att, nullptr, nullptr,
        3 * INNERD, 3 * INNERD, 3 * INNERD, SQ, 0,
        (long long)SQ * 3 * INNERD, (long long)SQ * 3 * INNERD,
        (long long)SQ * SQ, 0.125f);

    // 4) softmax rows + A-style split
    softmax_split<<<MTOK, 256>>>(att, at2);

    // 5) ao2 = split(attn @ V)   (per batch, M=2048, N=1024, K'=6144; split epilogue)
    gemm_nt<1><<<dim3(INNERD / 128, SQ / 128, NB), 128>>>(
        at2, v2, nullptr, ao2, nullptr,
        3 * SQ, 3 * SQ, 3 * SQ, 3 * INNERD, INNERD,
        (long long)SQ * 3 * SQ, (long long)INNERD * 3 * SQ,
        (long long)SQ * 3 * INNERD, 1.f);

    // 6) out = ao @ Wout + bias  (M=8192, N=1024, K'=3072)
    gemm_nt<0><<<dim3(DIMM / 128, MTOK / 128, 1), 128>>>(
        ao2, wo2, out, nullptr, bout,
        3 * INNERD, 3 * INNERD, 3 * INNERD, DIMM, 0, 0, 0, 0, 1.f);
}

// round 13
// speedup vs baseline: 1.9551x; 1.1119x over previous
#include <cuda_runtime.h>
#include <cuda_bf16.h>
#include <cstdint>
#include <math.h>

// Problem constants
#define NB     4
#define SQ     2048
#define DIMM   1024
#define INNERD 1024
#define MTOK   (NB * SQ)          // 8192

typedef __nv_bfloat16  bf16;
typedef __nv_bfloat162 bf162;

// ---------------- scratch (allocation-free rule: __device__ globals) ----------------
__device__ __align__(256) float g_qkv [(size_t)MTOK * 3 * INNERD];   // 96 MB fp32
__device__ __align__(256) float g_att [(size_t)MTOK * SQ];           // 64 MB fp32
__device__ __align__(256) bf16  g_x2  [(size_t)MTOK * 3 * DIMM];     // A-style split of x
__device__ __align__(256) bf16  g_q2  [(size_t)MTOK * 3 * INNERD];   // A-style split of Q
__device__ __align__(256) bf16  g_k2  [(size_t)MTOK * 3 * INNERD];   // B-style split of K
__device__ __align__(256) bf16  g_v2  [(size_t)NB * INNERD * 3 * SQ];// B-style transposed V
__device__ __align__(256) bf16  g_at2 [(size_t)MTOK * 3 * SQ];       // A-style split of attn
__device__ __align__(256) bf16  g_ao2 [(size_t)MTOK * 3 * INNERD];   // A-style split of attn@V
__device__ __align__(256) bf16  g_wq2 [(size_t)(3 * INNERD) * (3 * DIMM)]; // [3072, 3072]
__device__ __align__(256) bf16  g_wo2 [(size_t)DIMM * 3 * INNERD];   // [1024, 3072]

// ---------------- helpers ----------------
__device__ __forceinline__ uint32_t smem_u32(const void* p) {
    uint32_t a;
    asm("{ .reg .u64 t; cvta.to.shared.u64 t, %1; cvt.u32.u64 %0, t; }" : "=r"(a) : "l"(p));
    return a;
}
__device__ __forceinline__ void cpa16(uint32_t dst, const void* src) {
    asm volatile("cp.async.cg.shared.global [%0], [%1], 16;" :: "r"(dst), "l"(src));
}
__device__ __forceinline__ void cpa_commit() { asm volatile("cp.async.commit_group;"); }
__device__ __forceinline__ void cpa_wait1()  { asm volatile("cp.async.wait_group 1;" ::: "memory"); }

__device__ __forceinline__ void mma16(float* c, const unsigned* a, unsigned b0, unsigned b1) {
    asm volatile(
        "mma.sync.aligned.m16n8k16.row.col.f32.bf16.bf16.f32 "
        "{%0,%1,%2,%3}, {%4,%5,%6,%7}, {%8,%9}, {%0,%1,%2,%3};\n"
        : "+f"(c[0]), "+f"(c[1]), "+f"(c[2]), "+f"(c[3])
        : "r"(a[0]), "r"(a[1]), "r"(a[2]), "r"(a[3]), "r"(b0), "r"(b1));
}
__device__ __forceinline__ void ldsm4(uint32_t addr, unsigned* r) {
    asm volatile("ldmatrix.sync.aligned.m8n8.x4.shared.b16 {%0,%1,%2,%3}, [%4];"
        : "=r"(r[0]), "=r"(r[1]), "=r"(r[2]), "=r"(r[3]) : "r"(addr));
}
// swizzled byte offset in a [rows][64 bytes] tile, 16B-group q in 0..3
__device__ __forceinline__ int sw64(int row, int q) {
    return row * 64 + ((((unsigned)q) ^ (((unsigned)row >> 1) & 3)) << 4);
}
__device__ __forceinline__ void splitf2(float x, float y, bf162& h, bf162& l) {
    h = __floats2bfloat162_rn(x, y);
    l = __floats2bfloat162_rn(x - __low2float(h), y - __high2float(h));
}

// ---------------- plain bf16 NT GEMM, cp.async 3-stage pipeline ----------------
// C = alpha * A @ B^T (+bias)   A [M,Kp] bf16 ld lda, B [N,Kp] bf16 ld ldb.
// EPI 0: fp32 C.  EPI 1: bf16 split A-style output [h | l | h] with segment segN.
// CTA 128x128, KC=32, 128 threads = 4 warps (2m x 2n), warp tile 64x64.
// Running global pointers (no per-chunk address math); all-chunk frag preload.
template <int EPI>
__global__ __launch_bounds__(128)
void gemm_nt(const bf16* __restrict__ A, const bf16* __restrict__ B,
             float* __restrict__ C, bf16* __restrict__ C2,
             const float* __restrict__ bias,
             int Kp, int lda, int ldb, int ldc, int segN,
             long long bA, long long bB, long long bC, float alpha)
{
    __shared__ __align__(128) char sA[3 * 8192];
    __shared__ __align__(128) char sB[3 * 8192];
    const uint32_t uA = smem_u32(sA), uB = smem_u32(sB);

    const int tid = threadIdx.x;
    const int m0 = blockIdx.y * 128, n0 = blockIdx.x * 128;
    A += (long long)blockIdx.z * bA;
    B += (long long)blockIdx.z * bB;

    const int warp = tid >> 5, lane = tid & 31;
    const int wm = warp >> 1, wn = warp & 1;

    // fill mapping: row = (tid>>2) + 32*i, q = tid&3  (conflict-free phases)
    const int frow = tid >> 2;
    const int fq   = tid & 3;

    // Hoisted fill state: 8 running pointers + 8 fixed swizzled offsets.
    const bf16* pA[4]; const bf16* pB[4];
    uint32_t oA[4], oB[4];
    #pragma unroll
    for (int i = 0; i < 4; i++) {
        int r = frow + i * 32;
        pA[i] = A + (long long)(m0 + r) * lda + 8 * fq;
        pB[i] = B + (long long)(n0 + r) * ldb + 8 * fq;
        oA[i] = sw64(r, fq);
        oB[i] = sw64(r, fq);
    }

    auto fill = [&](int st) {
        const uint32_t da = uA + st * 8192, db = uB + st * 8192;
        #pragma unroll
        for (int i = 0; i < 4; i++) cpa16(da + oA[i], pA[i]);
        #pragma unroll
        for (int i = 0; i < 4; i++) cpa16(db + oB[i], pB[i]);
        cpa_commit();
        #pragma unroll
        for (int i = 0; i < 4; i++) { pA[i] += 32; pB[i] += 32; }
    };

    // ldmatrix components
    const int l15 = lane & 15;
    const int klh = lane >> 4;                    // k-half of k16 (0/1)
    const int sx  = ((l15 >> 1) & 3) << 4;        // swizzle XOR
    const int rA  = (wm * 64 + l15) * 64;
    const int rB  = (wn * 64 + l15) * 64;
    const int xo0 = (klh << 4) ^ sx;              // ks = 0
    const int xo1 = ((2 + klh) << 4) ^ sx;        // ks = 1

    float acc[4][8][4] = {};

    const int nch = Kp >> 5;
    fill(0);
    fill(1);

    for (int c = 0; c < nch; c++) {
        const int st = c % 3;
        cpa_wait1();                 // stage c data arrived
        __syncthreads();             // all warps done with stage (c+2)%3 from iter c-1
        if (c + 2 < nch) fill((c + 2) % 3);
        else             cpa_commit();       // keep group accounting aligned

        const uint32_t a0 = uA + st * 8192, b0 = uB + st * 8192;

        // Preload ALL fragments for both k16 halves, then stream 64 mma.
        unsigned fB0[4][4], fB1[4][4], fA0[4][4], fA1[4][4];
        #pragma unroll
        for (int p = 0; p < 4; p++) ldsm4(b0 + rB + p * 1024 + xo0, fB0[p]);
        #pragma unroll
        for (int p = 0; p < 4; p++) ldsm4(b0 + rB + p * 1024 + xo1, fB1[p]);
        #pragma unroll
        for (int mi = 0; mi < 4; mi++) ldsm4(a0 + rA + mi * 1024 + xo0, fA0[mi]);
        #pragma unroll
        for (int mi = 0; mi < 4; mi++) ldsm4(a0 + rA + mi * 1024 + xo1, fA1[mi]);

        #pragma unroll
        for (int mi = 0; mi < 4; mi++)
            #pragma unroll
            for (int p = 0; p < 4; p++) {
                mma16(acc[mi][2 * p    ], fA0[mi], fB0[p][0], fB0[p][2]);
                mma16(acc[mi][2 * p + 1], fA0[mi], fB0[p][1], fB0[p][3]);
            }
        #pragma unroll
        for (int mi = 0; mi < 4; mi++)
            #pragma unroll
            for (int p = 0; p < 4; p++) {
                mma16(acc[mi][2 * p    ], fA1[mi], fB1[p][0], fB1[p][2]);
                mma16(acc[mi][2 * p + 1], fA1[mi], fB1[p][1], fB1[p][3]);
            }
    }

    // ---- epilogue ----
    const int gid = lane >> 2, tig = lane & 3;
    if (EPI == 0) {
        C += (long long)blockIdx.z * bC;
        #pragma unroll
        for (int mi = 0; mi < 4; mi++) {
            #pragma unroll
            for (int ni = 0; ni < 8; ni++) {
                const int col  = n0 + wn * 64 + ni * 8 + 2 * tig;
                const int row0 = m0 + wm * 64 + mi * 16 + gid;
                float b0v = bias ? bias[col]     : 0.f;
                float b1v = bias ? bias[col + 1] : 0.f;
                float2 v0 = make_float2(acc[mi][ni][0] * alpha + b0v,
                                        acc[mi][ni][1] * alpha + b1v);
                float2 v1 = make_float2(acc[mi][ni][2] * alpha + b0v,
                                        acc[mi][ni][3] * alpha + b1v);
                *(float2*)(C + (long long)row0 * ldc + col)       = v0;
                *(float2*)(C + (long long)(row0 + 8) * ldc + col) = v1;
            }
        }
    } else {
        C2 += (long long)blockIdx.z * bC;
        #pragma unroll
        for (int mi = 0; mi < 4; mi++) {
            #pragma unroll
            for (int ni = 0; ni < 8; ni++) {
                const int col  = n0 + wn * 64 + ni * 8 + 2 * tig;
                const int row0 = m0 + wm * 64 + mi * 16 + gid;
                bf162 h2, l2;
                splitf2(acc[mi][ni][0], acc[mi][ni][1], h2, l2);
                bf16* p0 = C2 + (long long)row0 * ldc + col;
                *(bf162*)p0            = h2;
                *(bf162*)(p0 + segN)   = l2;
                *(bf162*)(p0 + 2*segN) = h2;
                splitf2(acc[mi][ni][2], acc[mi][ni][3], h2, l2);
                bf16* p1 = C2 + (long long)(row0 + 8) * ldc + col;
                *(bf162*)p1            = h2;
                *(bf162*)(p1 + segN)   = l2;
                *(bf162*)(p1 + 2*segN) = h2;
            }
        }
    }
}

// ---------------- split kernels ----------------
// Row-major split: in fp32 [R,C] (ld ldin) -> out bf16 [R,3C].
// STYLE 0 (A-side): [h | l | h]   STYLE 1 (B-side): [h | h | l]
template <int STYLE>
__global__ __launch_bounds__(256)
void split_rm(const float* __restrict__ in, bf16* __restrict__ out, int C, int ldin)
{
    const int r = blockIdx.y;
    const int j = (blockIdx.x * 256 + threadIdx.x) * 2;
    float2 v = *(const float2*)(in + (long long)r * ldin + j);
    bf162 h2, l2;
    splitf2(v.x, v.y, h2, l2);
    bf16* o = out + (long long)r * 3 * C + j;
    *(bf162*)o = h2;
    if (STYLE == 0) { *(bf162*)(o + C) = l2; *(bf162*)(o + 2 * C) = h2; }
    else            { *(bf162*)(o + C) = h2; *(bf162*)(o + 2 * C) = l2; }
}

// Transpose split (B-style): in fp32 [Krows, N] (ld ldin) -> out bf16 [N, 3*Kd].
__global__ __launch_bounds__(256)
void split_tr(const float* __restrict__ in, bf16* __restrict__ out,
              int ldin, int Kd, long long bIn, long long bOut)
{
    __shared__ float t[32][33];
    in  += (long long)blockIdx.z * bIn;
    out += (long long)blockIdx.z * bOut;
    const int k0 = blockIdx.y * 32, nn0 = blockIdx.x * 32;
    const int tx = threadIdx.x & 31, ty = threadIdx.x >> 5;
    #pragma unroll
    for (int i = 0; i < 4; i++)
        t[ty + 8 * i][tx] = in[(long long)(k0 + ty + 8 * i) * ldin + nn0 + tx];
    __syncthreads();
    #pragma unroll
    for (int i = 0; i < 4; i++) {
        float v = t[tx][ty + 8 * i];
        bf16 h = __float2bfloat16(v);
        bf16 l = __float2bfloat16(v - __bfloat162float(h));
        bf16* o = out + (long long)(nn0 + ty + 8 * i) * (3 * Kd) + k0 + tx;
        o[0] = h; o[Kd] = h; o[2 * Kd] = l;
    }
}

// ---------------- softmax + A-style split (fp32 [8192,2048] -> bf16 [8192,6144]) ----------------
__global__ __launch_bounds__(256)
void softmax_split(const float* __restrict__ att, bf16* __restrict__ out)
{
    const long long r = blockIdx.x;
    const float* row = att + r * 2048;
    bf16* orow = out + r * 6144;
    const int t = threadIdx.x;
    float2 v[4];
    float mx = -1e30f;
    #pragma unroll
    for (int j = 0; j < 4; j++) {
        v[j] = *(const float2*)(row + 2 * (t + j * 256));
        mx = fmaxf(mx, fmaxf(v[j].x, v[j].y));
    }
    __shared__ float red[256];
    red[t] = mx; __syncthreads();
    for (int s = 128; s > 0; s >>= 1) {
        if (t < s) red[t] = fmaxf(red[t], red[t + s]);
        __syncthreads();
    }
    mx = red[0]; __syncthreads();
    float sum = 0.f;
    #pragma unroll
    for (int j = 0; j < 4; j++) {
        v[j].x = __expf(v[j].x - mx);
        v[j].y = __expf(v[j].y - mx);
        sum += v[j].x + v[j].y;
    }
    red[t] = sum; __syncthreads();
    for (int s = 128; s > 0; s >>= 1) {
        if (t < s) red[t] += red[t + s];
        __syncthreads();
    }
    const float inv = 1.f / red[0];
    #pragma unroll
    for (int j = 0; j < 4; j++) {
        const int idx = 2 * (t + j * 256);
        bf162 h2, l2;
        splitf2(v[j].x * inv, v[j].y * inv, h2, l2);
        *(bf162*)(orow + idx)        = h2;
        *(bf162*)(orow + 2048 + idx) = l2;
        *(bf162*)(orow + 4096 + idx) = h2;
    }
}

// ---------------- launch ----------------
extern "C" void kernel_launch(void* const* d_in, const int* in_sizes, int n_in,
                              void* d_out, int out_size)
{
    const float* x    = (const float*)d_in[0];   // [4, 2048, 1024]
    const float* Wqkv = (const float*)d_in[1];   // [1024, 3072]
    const float* Wout = (const float*)d_in[2];   // [1024, 1024]
    const float* bout = (const float*)d_in[3];   // [1024]
    float* out = (float*)d_out;                  // [4, 2048, 1024]

    float *qkv, *att;
    bf16 *x2, *q2, *k2, *v2, *at2, *ao2, *wq2, *wo2;
    cudaGetSymbolAddress((void**)&qkv, g_qkv);
    cudaGetSymbolAddress((void**)&att, g_att);
    cudaGetSymbolAddress((void**)&x2,  g_x2);
    cudaGetSymbolAddress((void**)&q2,  g_q2);
    cudaGetSymbolAddress((void**)&k2,  g_k2);
    cudaGetSymbolAddress((void**)&v2,  g_v2);
    cudaGetSymbolAddress((void**)&at2, g_at2);
    cudaGetSymbolAddress((void**)&ao2, g_ao2);
    cudaGetSymbolAddress((void**)&wq2, g_wq2);
    cudaGetSymbolAddress((void**)&wo2, g_wo2);

    // 0) operand splits of the inputs
    split_rm<0><<<dim3(DIMM / 512, MTOK), 256>>>(x, x2, DIMM, DIMM);
    split_tr<<<dim3(3 * INNERD / 32, DIMM / 32, 1), 256>>>(Wqkv, wq2, 3 * INNERD, DIMM, 0, 0);
    split_tr<<<dim3(DIMM / 32, INNERD / 32, 1), 256>>>(Wout, wo2, DIMM, INNERD, 0, 0);

    // 1) qkv = x @ Wqkv          (M=8192, N=3072, K'=3072)
    gemm_nt<0><<<dim3(3 * INNERD / 128, MTOK / 128, 1), 128>>>(
        x2, wq2, qkv, nullptr, nullptr,
        3 * DIMM, 3 * DIMM, 3 * DIMM, 3 * INNERD, 0, 0, 0, 0, 1.f);

    // 2) splits of Q, K, V from qkv
    split_rm<0><<<dim3(2, MTOK), 256>>>(qkv,        q2, INNERD, 3 * INNERD);
    split_rm<1><<<dim3(2, MTOK), 256>>>(qkv + 1024, k2, INNERD, 3 * INNERD);
    split_tr<<<dim3(INNERD / 32, SQ / 32, NB), 256>>>(
        qkv + 2048, v2, 3 * INNERD, SQ,
        (long long)SQ * 3 * INNERD, (long long)INNERD * 3 * SQ);

    // 3) att = 0.125 * Q @ K^T   (per batch, M=N=2048, K'=3072)
    gemm_nt<0><<<dim3(SQ / 128, SQ / 128, NB), 128>>>(
        q2, k2, att, nullptr, nullptr,
        3 * INNERD, 3 * INNERD, 3 * INNERD, SQ, 0,
        (long long)SQ * 3 * INNERD, (long long)SQ * 3 * INNERD,
        (long long)SQ * SQ, 0.125f);

    // 4) softmax rows + A-style split
    softmax_split<<<MTOK, 256>>>(att, at2);

    // 5) ao2 = split(attn @ V)   (per batch, M=2048, N=1024, K'=6144; split epilogue)
    gemm_nt<1><<<dim3(INNERD / 128, SQ / 128, NB), 128>>>(
        at2, v2, nullptr, ao2, nullptr,
        3 * SQ, 3 * SQ, 3 * SQ, 3 * INNERD, INNERD,
        (long long)SQ * 3 * SQ, (long long)INNERD * 3 * SQ,
        (long long)SQ * 3 * INNERD, 1.f);

    // 6) out = ao @ Wout + bias  (M=8192, N=1024, K'=3072)
    gemm_nt<0><<<dim3(DIMM / 128, MTOK / 128, 1), 128>>>(
        ao2, wo2, out, nullptr, bout,
        3 * INNERD, 3 * INNERD, 3 * INNERD, DIMM, 0, 0, 0, 0, 1.f);
}

// round 14
// speedup vs baseline: 2.1453x; 1.0973x over previous
#include <cuda_runtime.h>
#include <cuda_bf16.h>
#include <cstdint>
#include <math.h>

// Problem constants
#define NB     4
#define SQ     2048
#define DIMM   1024
#define INNERD 1024
#define MTOK   (NB * SQ)          // 8192

typedef __nv_bfloat16  bf16;
typedef __nv_bfloat162 bf162;

// ---------------- scratch (allocation-free rule: __device__ globals) ----------------
__device__ __align__(256) float g_qkv [(size_t)MTOK * 3 * INNERD];   // 96 MB fp32
__device__ __align__(256) float g_att [(size_t)MTOK * SQ];           // 64 MB fp32
__device__ __align__(256) bf16  g_x2  [(size_t)MTOK * 3 * DIMM];     // A-style split of x
__device__ __align__(256) bf16  g_q2  [(size_t)MTOK * 3 * INNERD];   // A-style split of Q
__device__ __align__(256) bf16  g_k2  [(size_t)MTOK * 3 * INNERD];   // B-style split of K
__device__ __align__(256) bf16  g_v2  [(size_t)NB * INNERD * 3 * SQ];// B-style transposed V
__device__ __align__(256) bf16  g_at2 [(size_t)MTOK * 3 * SQ];       // A-style split of attn
__device__ __align__(256) bf16  g_ao2 [(size_t)MTOK * 3 * INNERD];   // A-style split of attn@V
__device__ __align__(256) bf16  g_wq2 [(size_t)(3 * INNERD) * (3 * DIMM)]; // [3072, 3072]
__device__ __align__(256) bf16  g_wo2 [(size_t)DIMM * 3 * INNERD];   // [1024, 3072]

// ---------------- helpers ----------------
__device__ __forceinline__ uint32_t smem_u32(const void* p) {
    uint32_t a;
    asm("{ .reg .u64 t; cvta.to.shared.u64 t, %1; cvt.u32.u64 %0, t; }" : "=r"(a) : "l"(p));
    return a;
}
__device__ __forceinline__ void cpa16(uint32_t dst, const void* src) {
    asm volatile("cp.async.cg.shared.global [%0], [%1], 16;" :: "r"(dst), "l"(src));
}
__device__ __forceinline__ void cpa_commit() { asm volatile("cp.async.commit_group;"); }
__device__ __forceinline__ void cpa_wait1()  { asm volatile("cp.async.wait_group 1;" ::: "memory"); }

__device__ __forceinline__ void mma16(float* c, const unsigned* a, unsigned b0, unsigned b1) {
    asm volatile(
        "mma.sync.aligned.m16n8k16.row.col.f32.bf16.bf16.f32 "
        "{%0,%1,%2,%3}, {%4,%5,%6,%7}, {%8,%9}, {%0,%1,%2,%3};\n"
        : "+f"(c[0]), "+f"(c[1]), "+f"(c[2]), "+f"(c[3])
        : "r"(a[0]), "r"(a[1]), "r"(a[2]), "r"(a[3]), "r"(b0), "r"(b1));
}
__device__ __forceinline__ void ldsm4(uint32_t addr, unsigned* r) {
    asm volatile("ldmatrix.sync.aligned.m8n8.x4.shared.b16 {%0,%1,%2,%3}, [%4];"
        : "=r"(r[0]), "=r"(r[1]), "=r"(r[2]), "=r"(r[3]) : "r"(addr));
}
// swizzled byte offset in a [rows][64 bytes] tile, 16B-group q in 0..3
__device__ __forceinline__ int sw64(int row, int q) {
    return row * 64 + ((((unsigned)q) ^ (((unsigned)row >> 1) & 3)) << 4);
}
__device__ __forceinline__ void splitf2(float x, float y, bf162& h, bf162& l) {
    h = __floats2bfloat162_rn(x, y);
    l = __floats2bfloat162_rn(x - __low2float(h), y - __high2float(h));
}

// ---------------- plain bf16 NT GEMM, cp.async 3-stage pipeline ----------------
// C = alpha * A @ B^T (+bias)   A [M,Kp] bf16 ld lda, B [N,Kp] bf16 ld ldb.
// EPI 0: fp32 C.  EPI 1: bf16 split A-style output [h | l | h] with segment segN.
// CTA 128x128, KC=32, 128 threads = 4 warps (2m x 2n), warp tile 64x64.
// Cross-chunk fragment software pipeline; stage bases constant via 3x unroll.
template <int EPI>
__global__ __launch_bounds__(128, 2)
void gemm_nt(const bf16* __restrict__ A, const bf16* __restrict__ B,
             float* __restrict__ C, bf16* __restrict__ C2,
             const float* __restrict__ bias,
             int Kp, int lda, int ldb, int ldc, int segN,
             long long bA, long long bB, long long bC, float alpha)
{
    __shared__ __align__(128) char sA[3 * 8192];
    __shared__ __align__(128) char sB[3 * 8192];
    const uint32_t uA = smem_u32(sA), uB = smem_u32(sB);

    const int tid = threadIdx.x;
    const int m0 = blockIdx.y * 128, n0 = blockIdx.x * 128;
    A += (long long)blockIdx.z * bA;
    B += (long long)blockIdx.z * bB;

    const int warp = tid >> 5, lane = tid & 31;
    const int wm = warp >> 1, wn = warp & 1;

    // fill mapping: row = (tid>>2) + 32*i, q = tid&3  (conflict-free phases)
    const int frow = tid >> 2;
    const int fq   = tid & 3;

    // Hoisted fill state: running pointers + fixed swizzled offsets.
    const bf16* pA[4]; const bf16* pB[4];
    uint32_t oX[4];
    #pragma unroll
    for (int i = 0; i < 4; i++) {
        int r = frow + i * 32;
        pA[i] = A + (long long)(m0 + r) * lda + 8 * fq;
        pB[i] = B + (long long)(n0 + r) * ldb + 8 * fq;
        oX[i] = sw64(r, fq);
    }

    auto fill_to = [&](uint32_t da, uint32_t db) {
        #pragma unroll
        for (int i = 0; i < 4; i++) cpa16(da + oX[i], pA[i]);
        #pragma unroll
        for (int i = 0; i < 4; i++) cpa16(db + oX[i], pB[i]);
        cpa_commit();
        #pragma unroll
        for (int i = 0; i < 4; i++) { pA[i] += 32; pB[i] += 32; }
    };

    // ldmatrix components
    const int l15 = lane & 15;
    const int klh = lane >> 4;                    // k-half of k16 (0/1)
    const int sx  = ((l15 >> 1) & 3) << 4;        // swizzle XOR
    const int rA  = (wm * 64 + l15) * 64;
    const int rB  = (wn * 64 + l15) * 64;
    const int xo0 = (klh << 4) ^ sx;              // ks = 0
    const int xo1 = ((2 + klh) << 4) ^ sx;        // ks = 1

    float acc[4][8][4] = {};
    unsigned fA0[4][4], fB0[4][4], fA1[4][4], fB1[4][4];

    const int nch = Kp >> 5;    // divisible by 3 for all our shapes

    // Preamble: fill stages 0,1; wait stage 0; load chunk-0 ks0 fragments.
    fill_to(uA, uB);
    fill_to(uA + 8192, uB + 8192);
    cpa_wait1();
    __syncthreads();
    #pragma unroll
    for (int p = 0; p < 4; p++) ldsm4(uB + rB + p * 1024 + xo0, fB0[p]);
    #pragma unroll
    for (int mi = 0; mi < 4; mi++) ldsm4(uA + rA + mi * 1024 + xo0, fA0[mi]);

    // One chunk: a0/b0 = current stage, a1/b1 = next stage, a2/b2 = fill target.
    auto step = [&](uint32_t a0, uint32_t b0, uint32_t a1, uint32_t b1,
                    uint32_t a2, uint32_t b2, int c) {
        // Fill 2-ahead (prev sync guarantees that stage's readers are done).
        if (c + 2 < nch) fill_to(a2, b2);
        else             cpa_commit();
        // ks1 fragments of the current chunk (consumed after ks0 stream).
        #pragma unroll
        for (int p = 0; p < 4; p++) ldsm4(b0 + rB + p * 1024 + xo1, fB1[p]);
        #pragma unroll
        for (int mi = 0; mi < 4; mi++) ldsm4(a0 + rA + mi * 1024 + xo1, fA1[mi]);
        // 64 back-to-back mma
        #pragma unroll
        for (int mi = 0; mi < 4; mi++)
            #pragma unroll
            for (int p = 0; p < 4; p++) {
                mma16(acc[mi][2 * p    ], fA0[mi], fB0[p][0], fB0[p][2]);
                mma16(acc[mi][2 * p + 1], fA0[mi], fB0[p][1], fB0[p][3]);
            }
        #pragma unroll
        for (int mi = 0; mi < 4; mi++)
            #pragma unroll
            for (int p = 0; p < 4; p++) {
                mma16(acc[mi][2 * p    ], fA1[mi], fB1[p][0], fB1[p][2]);
                mma16(acc[mi][2 * p + 1], fA1[mi], fB1[p][1], fB1[p][3]);
            }
        // stage c+1 arrived (everywhere) -> barrier -> prefetch its ks0 frags.
        cpa_wait1();
        __syncthreads();
        #pragma unroll
        for (int p = 0; p < 4; p++) ldsm4(b1 + rB + p * 1024 + xo0, fB0[p]);
        #pragma unroll
        for (int mi = 0; mi < 4; mi++) ldsm4(a1 + rA + mi * 1024 + xo0, fA0[mi]);
    };

    for (int c = 0; c < nch; c += 3) {
        step(uA,         uB,         uA + 8192,  uB + 8192,  uA + 16384, uB + 16384, c);
        step(uA + 8192,  uB + 8192,  uA + 16384, uB + 16384, uA,         uB,         c + 1);
        step(uA + 16384, uB + 16384, uA,         uB,         uA + 8192,  uB + 8192,  c + 2);
    }

    // ---- epilogue ----
    const int gid = lane >> 2, tig = lane & 3;
    if (EPI == 0) {
        C += (long long)blockIdx.z * bC;
        #pragma unroll
        for (int mi = 0; mi < 4; mi++) {
            #pragma unroll
            for (int ni = 0; ni < 8; ni++) {
                const int col  = n0 + wn * 64 + ni * 8 + 2 * tig;
                const int row0 = m0 + wm * 64 + mi * 16 + gid;
                float b0v = bias ? bias[col]     : 0.f;
                float b1v = bias ? bias[col + 1] : 0.f;
                float2 v0 = make_float2(acc[mi][ni][0] * alpha + b0v,
                                        acc[mi][ni][1] * alpha + b1v);
                float2 v1 = make_float2(acc[mi][ni][2] * alpha + b0v,
                                        acc[mi][ni][3] * alpha + b1v);
                *(float2*)(C + (long long)row0 * ldc + col)       = v0;
                *(float2*)(C + (long long)(row0 + 8) * ldc + col) = v1;
            }
        }
    } else {
        C2 += (long long)blockIdx.z * bC;
        #pragma unroll
        for (int mi = 0; mi < 4; mi++) {
            #pragma unroll
            for (int ni = 0; ni < 8; ni++) {
                const int col  = n0 + wn * 64 + ni * 8 + 2 * tig;
                const int row0 = m0 + wm * 64 + mi * 16 + gid;
                bf162 h2, l2;
                splitf2(acc[mi][ni][0], acc[mi][ni][1], h2, l2);
                bf16* p0 = C2 + (long long)row0 * ldc + col;
                *(bf162*)p0            = h2;
                *(bf162*)(p0 + segN)   = l2;
                *(bf162*)(p0 + 2*segN) = h2;
                splitf2(acc[mi][ni][2], acc[mi][ni][3], h2, l2);
                bf16* p1 = C2 + (long long)(row0 + 8) * ldc + col;
                *(bf162*)p1            = h2;
                *(bf162*)(p1 + segN)   = l2;
                *(bf162*)(p1 + 2*segN) = h2;
            }
        }
    }
}

// ---------------- split kernels ----------------
// Row-major split: in fp32 [R,C] (ld ldin) -> out bf16 [R,3C].
// STYLE 0 (A-side): [h | l | h]   STYLE 1 (B-side): [h | h | l]
template <int STYLE>
__global__ __launch_bounds__(256)
void split_rm(const float* __restrict__ in, bf16* __restrict__ out, int C, int ldin)
{
    const int r = blockIdx.y;
    const int j = (blockIdx.x * 256 + threadIdx.x) * 2;
    float2 v = *(const float2*)(in + (long long)r * ldin + j);
    bf162 h2, l2;
    splitf2(v.x, v.y, h2, l2);
    bf16* o = out + (long long)r * 3 * C + j;
    *(bf162*)o = h2;
    if (STYLE == 0) { *(bf162*)(o + C) = l2; *(bf162*)(o + 2 * C) = h2; }
    else            { *(bf162*)(o + C) = h2; *(bf162*)(o + 2 * C) = l2; }
}

// Transpose split (B-style): in fp32 [Krows, N] (ld ldin) -> out bf16 [N, 3*Kd].
__global__ __launch_bounds__(256)
void split_tr(const float* __restrict__ in, bf16* __restrict__ out,
              int ldin, int Kd, long long bIn, long long bOut)
{
    __shared__ float t[32][33];
    in  += (long long)blockIdx.z * bIn;
    out += (long long)blockIdx.z * bOut;
    const int k0 = blockIdx.y * 32, nn0 = blockIdx.x * 32;
    const int tx = threadIdx.x & 31, ty = threadIdx.x >> 5;
    #pragma unroll
    for (int i = 0; i < 4; i++)
        t[ty + 8 * i][tx] = in[(long long)(k0 + ty + 8 * i) * ldin + nn0 + tx];
    __syncthreads();
    #pragma unroll
    for (int i = 0; i < 4; i++) {
        float v = t[tx][ty + 8 * i];
        bf16 h = __float2bfloat16(v);
        bf16 l = __float2bfloat16(v - __bfloat162float(h));
        bf16* o = out + (long long)(nn0 + ty + 8 * i) * (3 * Kd) + k0 + tx;
        o[0] = h; o[Kd] = h; o[2 * Kd] = l;
    }
}

// ---------------- softmax + A-style split (fp32 [8192,2048] -> bf16 [8192,6144]) ----------------
__global__ __launch_bounds__(256)
void softmax_split(const float* __restrict__ att, bf16* __restrict__ out)
{
    const long long r = blockIdx.x;
    const float* row = att + r * 2048;
    bf16* orow = out + r * 6144;
    const int t = threadIdx.x;
    float2 v[4];
    float mx = -1e30f;
    #pragma unroll
    for (int j = 0; j < 4; j++) {
        v[j] = *(const float2*)(row + 2 * (t + j * 256));
        mx = fmaxf(mx, fmaxf(v[j].x, v[j].y));
    }
    __shared__ float red[256];
    red[t] = mx; __syncthreads();
    for (int s = 128; s > 0; s >>= 1) {
        if (t < s) red[t] = fmaxf(red[t], red[t + s]);
        __syncthreads();
    }
    mx = red[0]; __syncthreads();
    float sum = 0.f;
    #pragma unroll
    for (int j = 0; j < 4; j++) {
        v[j].x = __expf(v[j].x - mx);
        v[j].y = __expf(v[j].y - mx);
        sum += v[j].x + v[j].y;
    }
    red[t] = sum; __syncthreads();
    for (int s = 128; s > 0; s >>= 1) {
        if (t < s) red[t] += red[t + s];
        __syncthreads();
    }
    const float inv = 1.f / red[0];
    #pragma unroll
    for (int j = 0; j < 4; j++) {
        const int idx = 2 * (t + j * 256);
        bf162 h2, l2;
        splitf2(v[j].x * inv, v[j].y * inv, h2, l2);
        *(bf162*)(orow + idx)        = h2;
        *(bf162*)(orow + 2048 + idx) = l2;
        *(bf162*)(orow + 4096 + idx) = h2;
    }
}

// ---------------- launch ----------------
extern "C" void kernel_launch(void* const* d_in, const int* in_sizes, int n_in,
                              void* d_out, int out_size)
{
    const float* x    = (const float*)d_in[0];   // [4, 2048, 1024]
    const float* Wqkv = (const float*)d_in[1];   // [1024, 3072]
    const float* Wout = (const float*)d_in[2];   // [1024, 1024]
    const float* bout = (const float*)d_in[3];   // [1024]
    float* out = (float*)d_out;                  // [4, 2048, 1024]

    float *qkv, *att;
    bf16 *x2, *q2, *k2, *v2, *at2, *ao2, *wq2, *wo2;
    cudaGetSymbolAddress((void**)&qkv, g_qkv);
    cudaGetSymbolAddress((void**)&att, g_att);
    cudaGetSymbolAddress((void**)&x2,  g_x2);
    cudaGetSymbolAddress((void**)&q2,  g_q2);
    cudaGetSymbolAddress((void**)&k2,  g_k2);
    cudaGetSymbolAddress((void**)&v2,  g_v2);
    cudaGetSymbolAddress((void**)&at2, g_at2);
    cudaGetSymbolAddress((void**)&ao2, g_ao2);
    cudaGetSymbolAddress((void**)&wq2, g_wq2);
    cudaGetSymbolAddress((void**)&wo2, g_wo2);

    // 0) operand splits of the inputs
    split_rm<0><<<dim3(DIMM / 512, MTOK), 256>>>(x, x2, DIMM, DIMM);
    split_tr<<<dim3(3 * INNERD / 32, DIMM / 32, 1), 256>>>(Wqkv, wq2, 3 * INNERD, DIMM, 0, 0);
    split_tr<<<dim3(DIMM / 32, INNERD / 32, 1), 256>>>(Wout, wo2, DIMM, INNERD, 0, 0);

    // 1) qkv = x @ Wqkv          (M=8192, N=3072, K'=3072)
    gemm_nt<0><<<dim3(3 * INNERD / 128, MTOK / 128, 1), 128>>>(
        x2, wq2, qkv, nullptr, nullptr,
        3 * DIMM, 3 * DIMM, 3 * DIMM, 3 * INNERD, 0, 0, 0, 0, 1.f);

    // 2) splits of Q, K, V from qkv
    split_rm<0><<<dim3(2, MTOK), 256>>>(qkv,        q2, INNERD, 3 * INNERD);
    split_rm<1><<<dim3(2, MTOK), 256>>>(qkv + 1024, k2, INNERD, 3 * INNERD);
    split_tr<<<dim3(INNERD / 32, SQ / 32, NB), 256>>>(
        qkv + 2048, v2, 3 * INNERD, SQ,
        (long long)SQ * 3 * INNERD, (long long)INNERD * 3 * SQ);

    // 3) att = 0.125 * Q @ K^T   (per batch, M=N=2048, K'=3072)
    gemm_nt<0><<<dim3(SQ / 128, SQ / 128, NB), 128>>>(
        q2, k2, att, nullptr, nullptr,
        3 * INNERD, 3 * INNERD, 3 * INNERD, SQ, 0,
        (long long)SQ * 3 * INNERD, (long long)SQ * 3 * INNERD,
        (long long)SQ * SQ, 0.125f);

    // 4) softmax rows + A-style split
    softmax_split<<<MTOK, 256>>>(att, at2);

    // 5) ao2 = split(attn @ V)   (per batch, M=2048, N=1024, K'=6144; split epilogue)
    gemm_nt<1><<<dim3(INNERD / 128, SQ / 128, NB), 128>>>(
        at2, v2, nullptr, ao2, nullptr,
        3 * SQ, 3 * SQ, 3 * SQ, 3 * INNERD, INNERD,
        (long long)SQ * 3 * SQ, (long long)INNERD * 3 * SQ,
        (long long)SQ * 3 * INNERD, 1.f);

    // 6) out = ao @ Wout + bias  (M=8192, N=1024, K'=3072)
    gemm_nt<0><<<dim3(DIMM / 128, MTOK / 128, 1), 128>>>(
        ao2, wo2, out, nullptr, bout,
        3 * INNERD, 3 * INNERD, 3 * INNERD, DIMM, 0, 0, 0, 0, 1.f);
}